// round 3
// baseline (speedup 1.0000x reference)
#include <cuda_runtime.h>
#include <math.h>

#define LEVELS 4
#define KCB    1024
#define DIM    64
#define NVEC   131072        // 16 * 8192
#define BLK    256
#define CHUNK  64            // codewords staged in shared per iteration

// out layout: [NVEC*DIM quantized][LEVELS*NVEC codes][1 loss]
#define QELEMS ((size_t)NVEC * DIM)

#define NEG1X2 0xBF800000BF800000ULL   // packed {-1.0f, -1.0f}

// Scratch (no device allocation allowed)
__device__ double g_mse[LEVELS];
__device__ int    g_counts[LEVELS * KCB];
__device__ float  g_c2[LEVELS * KCB];

// ---- packed f32x2 helpers (sm_100+ PTX; 2 fp32 ops per instruction) ----
__device__ __forceinline__ unsigned long long ffma2(unsigned long long a,
                                                    unsigned long long b,
                                                    unsigned long long c) {
    unsigned long long d;
    asm("fma.rn.f32x2 %0, %1, %2, %3;" : "=l"(d) : "l"(a), "l"(b), "l"(c));
    return d;
}
__device__ __forceinline__ unsigned long long fadd2(unsigned long long a,
                                                    unsigned long long b) {
    unsigned long long d;
    asm("add.rn.f32x2 %0, %1, %2;" : "=l"(d) : "l"(a), "l"(b));
    return d;
}
__device__ __forceinline__ float hsum2(unsigned long long a) {
    float lo, hi;
    asm("mov.b64 {%0, %1}, %2;" : "=f"(lo), "=f"(hi) : "l"(a));
    return lo + hi;
}

__global__ void zero_kernel() {
    int t = blockIdx.x * blockDim.x + threadIdx.x;
    if (t < LEVELS) g_mse[t] = 0.0;
    if (t < LEVELS * KCB) g_counts[t] = 0;
}

__global__ void c2_kernel(const float* __restrict__ cb) {
    int t = blockIdx.x * blockDim.x + threadIdx.x;   // 0..4095
    if (t < LEVELS * KCB) {
        const float* v = cb + (size_t)t * DIM;
        float s = 0.f;
        #pragma unroll
        for (int d = 0; d < DIM; ++d) s += v[d] * v[d];
        g_c2[t] = s;
    }
}

__global__ __launch_bounds__(BLK, 2)
void rvq_kernel(const float* __restrict__ x,
                const float* __restrict__ cb,
                float* __restrict__ out) {
    __shared__ float  scb[CHUNK][DIM];        // 16 KB codebook chunk
    __shared__ float  sc2[CHUNK];
    __shared__ double sred[BLK / 32];

    const int n = blockIdx.x * BLK + threadIdx.x;    // one vector per thread

    // Residual lives in registers as 32 packed f32x2 (= 64 floats).
    // A ulonglong2 is 16B = 4 floats, so one 64-float vector = 16 ulonglong2.
    unsigned long long r[32];
    const ulonglong2* xv = (const ulonglong2*)(x + (size_t)n * DIM);
    #pragma unroll
    for (int i = 0; i < 16; ++i) {
        ulonglong2 v = xv[i];
        r[2*i] = v.x; r[2*i + 1] = v.y;
    }

    for (int l = 0; l < LEVELS; ++l) {
        const float* cbl = cb + (size_t)l * KCB * DIM;
        float best = 3.402823466e38f;
        int   bidx = 0;

        for (int c0 = 0; c0 < KCB; c0 += CHUNK) {
            __syncthreads();   // protect previous chunk's readers
            // cooperative coalesced load of CHUNK codewords + their norms
            {
                const float4* src = (const float4*)(cbl + (size_t)c0 * DIM);
                float4* dst = (float4*)&scb[0][0];
                #pragma unroll
                for (int i = threadIdx.x; i < CHUNK * DIM / 4; i += BLK)
                    dst[i] = src[i];
                if (threadIdx.x < CHUNK)
                    sc2[threadIdx.x] = g_c2[l * KCB + c0 + threadIdx.x];
            }
            __syncthreads();

            #pragma unroll 1
            for (int c = 0; c < CHUNK; ++c) {
                // warp-uniform address -> broadcast LDS.128, two packed
                // f32x2 operands per load, no packing instructions
                const ulonglong2* w = (const ulonglong2*)scb[c];
                unsigned long long a0 = 0ull, a1 = 0ull;
                #pragma unroll
                for (int i = 0; i < 16; ++i) {
                    ulonglong2 wv = w[i];
                    a0 = ffma2(r[2*i],     wv.x, a0);
                    a1 = ffma2(r[2*i + 1], wv.y, a1);
                }
                float s = hsum2(fadd2(a0, a1));
                float dist = fmaf(-2.f, s, sc2[c]);
                if (dist < best) { best = dist; bidx = c0 + c; }   // first-min
            }
        }

        atomicAdd(&g_counts[l * KCB + bidx], 1);

        // subtract chosen codeword (exact: fma with -1), accumulate residual^2
        const ulonglong2* q = (const ulonglong2*)(cbl + (size_t)bidx * DIM);
        unsigned long long sacc0 = 0ull, sacc1 = 0ull;
        #pragma unroll
        for (int i = 0; i < 16; ++i) {
            ulonglong2 qv = q[i];
            r[2*i]     = ffma2(qv.x, NEG1X2, r[2*i]);
            r[2*i + 1] = ffma2(qv.y, NEG1X2, r[2*i + 1]);
            sacc0 = ffma2(r[2*i],     r[2*i],     sacc0);
            sacc1 = ffma2(r[2*i + 1], r[2*i + 1], sacc1);
        }
        float sse = hsum2(fadd2(sacc0, sacc1));

        // block-reduce sse (double) -> one atomic per block per level
        double ds = (double)sse;
        #pragma unroll
        for (int o = 16; o; o >>= 1) ds += __shfl_down_sync(0xffffffffu, ds, o);
        if ((threadIdx.x & 31) == 0) sred[threadIdx.x >> 5] = ds;
        __syncthreads();
        if (threadIdx.x == 0) {
            double t = 0.0;
            #pragma unroll
            for (int w = 0; w < BLK / 32; ++w) t += sred[w];
            atomicAdd(&g_mse[l], t);
        }

        // codes: [levels, N], cast to output dtype (f32)
        out[QELEMS + (size_t)l * NVEC + n] = (float)bidx;
    }

    // quantized_out = x - final_residual (packed, exact)
    ulonglong2* qo = (ulonglong2*)(out + (size_t)n * DIM);
    #pragma unroll
    for (int i = 0; i < 16; ++i) {
        ulonglong2 xp = xv[i];
        ulonglong2 o2;
        o2.x = ffma2(r[2*i],     NEG1X2, xp.x);
        o2.y = ffma2(r[2*i + 1], NEG1X2, xp.y);
        qo[i] = o2;
    }
}

__global__ void finalize_kernel(float* __restrict__ out) {
    __shared__ double warpsum[8];
    const int t = threadIdx.x;     // 256 threads
    double total = 0.0;
    for (int l = 0; l < LEVELS; ++l) {
        float esum = 0.f;          // fp32 to match jax's fp32 entropy math
        for (int i = t; i < KCB; i += 256) {
            float p = (float)g_counts[l * KCB + i] / (float)NVEC;
            esum += -(p * logf(p + 1e-10f));
        }
        double e = (double)esum;
        #pragma unroll
        for (int o = 16; o; o >>= 1) e += __shfl_down_sync(0xffffffffu, e, o);
        if ((t & 31) == 0) warpsum[t >> 5] = e;
        __syncthreads();
        if (t == 0) {
            double ent = 0.0;
            #pragma unroll
            for (int w = 0; w < 8; ++w) ent += warpsum[w];
            double mse = g_mse[l] / ((double)NVEC * DIM);
            // rec_loss + com_loss = (1 + 0.25) * mean(new_residual^2)
            total += 1.25 * mse + 0.1 * ent;
        }
        __syncthreads();
    }
    if (t == 0) out[QELEMS + (size_t)LEVELS * NVEC] = (float)total;
}

extern "C" void kernel_launch(void* const* d_in, const int* in_sizes, int n_in,
                              void* d_out, int out_size) {
    const float* x  = (const float*)d_in[0];   // [16,8192,64] f32
    const float* cb = (const float*)d_in[1];   // [4,1024,64]  f32
    float* out = (float*)d_out;

    zero_kernel<<<16, 256>>>();
    c2_kernel<<<16, 256>>>(cb);
    rvq_kernel<<<NVEC / BLK, BLK>>>(x, cb, out);
    finalize_kernel<<<1, 256>>>(out);
}

// round 5
// speedup vs baseline: 3.7981x; 3.7981x over previous
#include <cuda_runtime.h>
#include <cuda_bf16.h>
#include <math.h>
#include <stdint.h>

#define LEVELS 4
#define KCB    1024
#define DIM    64
#define NVEC   131072
#define CTAV   128            // vectors per CTA
#define NTHR   256
#define CHUNK  128            // codewords staged per chunk
#define QELEMS ((size_t)NVEC * DIM)
#define MARGIN 0.03f
#define STRH   72             // halves per staged row (stride, conflict-free)
#define STRB   144            // bytes per staged row

// ---------------- device scratch (no allocs allowed) ----------------
__device__ double        g_mse[LEVELS];
__device__ int           g_counts[LEVELS * KCB];
__device__ float         g_c2[LEVELS * KCB];
__device__ __nv_bfloat16 g_cbh[LEVELS * KCB * DIM];   // row-major [4096][64]
__device__ __nv_bfloat16 g_cbl[LEVELS * KCB * DIM];

// ---------------- SMEM layout (dynamic, bytes) ----------------
#define SM_AH     0                    // 128 rows * 144B = 18432
#define SM_AL     18432
#define SM_BH     36864                // 128 rows * 144B
#define SM_BL     55296
#define SM_C2     73728                // 128 f32
#define SM_IDX    74240                // 128 i32
#define SM_LIST   74752                // 128 i32
#define SM_RSTAGE 75264                // 64 f32
#define SM_NLIST  75520
#define SM_REDK   75528
#define SMEM_TOTAL 75552

// ---------------- helpers ----------------
__device__ __forceinline__ uint32_t smem_u32(const void* p) {
    uint32_t a;
    asm("{ .reg .u64 t; cvta.to.shared.u64 t, %1; cvt.u32.u64 %0, t; }"
        : "=r"(a) : "l"(p));
    return a;
}
__device__ __forceinline__ void ldsm4(uint32_t r[4], uint32_t addr) {
    asm volatile("ldmatrix.sync.aligned.m8n8.x4.shared.b16 {%0,%1,%2,%3}, [%4];"
                 : "=r"(r[0]), "=r"(r[1]), "=r"(r[2]), "=r"(r[3]) : "r"(addr));
}
__device__ __forceinline__ void mma16816(float* d, const uint32_t* a,
                                         uint32_t b0, uint32_t b1) {
    asm volatile(
        "mma.sync.aligned.m16n8k16.row.col.f32.bf16.bf16.f32 "
        "{%0,%1,%2,%3}, {%4,%5,%6,%7}, {%8,%9}, {%0,%1,%2,%3};"
        : "+f"(d[0]), "+f"(d[1]), "+f"(d[2]), "+f"(d[3])
        : "r"(a[0]), "r"(a[1]), "r"(a[2]), "r"(a[3]), "r"(b0), "r"(b1));
}
__device__ __forceinline__ void track(float d, int idx,
                                      float& m1, int& i1, float& m2) {
    if (d < m1)      { m2 = m1; m1 = d; i1 = idx; }
    else if (d < m2) { m2 = d; }
}
__device__ __forceinline__ void merge3(float& m1, int& i1, float& m2,
                                       float om1, int oi1, float om2) {
    if (om1 < m1 || (om1 == m1 && oi1 < i1)) {
        m2 = fminf(m1, om2); m1 = om1; i1 = oi1;
    } else {
        m2 = fminf(m2, om1);
    }
}

// ---------------- small kernels ----------------
__global__ void zero_kernel() {
    int t = blockIdx.x * blockDim.x + threadIdx.x;
    if (t < LEVELS) g_mse[t] = 0.0;
    if (t < LEVELS * KCB) g_counts[t] = 0;
}

__global__ void prep_cb_kernel(const float* __restrict__ cb) {
    int t = blockIdx.x * blockDim.x + threadIdx.x;   // one codeword row
    if (t >= LEVELS * KCB) return;
    const float* v = cb + (size_t)t * DIM;
    __nv_bfloat16* dh = g_cbh + (size_t)t * DIM;
    __nv_bfloat16* dl = g_cbl + (size_t)t * DIM;
    float s = 0.f;
    #pragma unroll
    for (int d = 0; d < DIM; ++d) {
        float f = v[d];
        s += f * f;
        __nv_bfloat16 hi = __float2bfloat16(f);
        dh[d] = hi;
        dl[d] = __float2bfloat16(f - __bfloat162float(hi));
    }
    g_c2[t] = s;
}

// ---------------- main kernel ----------------
__global__ __launch_bounds__(NTHR, 2)
void rvq_mma_kernel(const float* __restrict__ x,
                    const float* __restrict__ cb,
                    float* __restrict__ out) {
    extern __shared__ char smem[];
    const uint32_t sb = smem_u32(smem);
    const int tid  = threadIdx.x;
    const int lane = tid & 31, warp = tid >> 5;
    const int v = tid >> 1, h = tid & 1;             // owner: vector v, half h
    const size_t n0 = (size_t)blockIdx.x * CTAV;

    int*    sidx   = (int*)(smem + SM_IDX);
    float*  sc2    = (float*)(smem + SM_C2);
    int*    list   = (int*)(smem + SM_LIST);
    float*  rstage = (float*)(smem + SM_RSTAGE);
    int*    nlist  = (int*)(smem + SM_NLIST);
    unsigned long long* redk = (unsigned long long*)(smem + SM_REDK);

    // residual: this thread owns 32 dims of vector v
    float r[32];
    {
        const float4* xp = (const float4*)(x + (n0 + v) * DIM + h * 32);
        #pragma unroll
        for (int i = 0; i < 8; ++i) {
            float4 t4 = xp[i];
            r[4*i] = t4.x; r[4*i+1] = t4.y; r[4*i+2] = t4.z; r[4*i+3] = t4.w;
        }
    }

    for (int l = 0; l < LEVELS; ++l) {
        // ---- stage A hi/lo (bf16, stride 72 halves) ----
        #pragma unroll
        for (int i = 0; i < 16; ++i) {
            float a0 = r[2*i], a1 = r[2*i+1];
            __nv_bfloat16 h0 = __float2bfloat16(a0), h1 = __float2bfloat16(a1);
            __nv_bfloat16 l0 = __float2bfloat16(a0 - __bfloat162float(h0));
            __nv_bfloat16 l1 = __float2bfloat16(a1 - __bfloat162float(h1));
            uint32_t wh = (uint32_t)__bfloat16_as_ushort(h0) |
                          ((uint32_t)__bfloat16_as_ushort(h1) << 16);
            uint32_t wl = (uint32_t)__bfloat16_as_ushort(l0) |
                          ((uint32_t)__bfloat16_as_ushort(l1) << 16);
            int off = v * STRB + (h * 32 + 2*i) * 2;
            *(uint32_t*)(smem + SM_AH + off) = wh;
            *(uint32_t*)(smem + SM_AL + off) = wl;
        }
        if (tid == 0) *nlist = 0;
        __syncthreads();

        // ---- load A fragments (held all level) ----
        uint32_t Ah[4][4], Al[4][4];
        {
            int rowA = warp * 16 + (lane >> 2);
            int cc   = (lane & 3) * 2;
            #pragma unroll
            for (int ks = 0; ks < 4; ++ks) {
                int kb = ks * 16 + cc;
                int o00 = rowA * STRB + kb * 2;
                int o10 = (rowA + 8) * STRB + kb * 2;
                Ah[ks][0] = *(const uint32_t*)(smem + SM_AH + o00);
                Ah[ks][1] = *(const uint32_t*)(smem + SM_AH + o10);
                Ah[ks][2] = *(const uint32_t*)(smem + SM_AH + o00 + 16);
                Ah[ks][3] = *(const uint32_t*)(smem + SM_AH + o10 + 16);
                Al[ks][0] = *(const uint32_t*)(smem + SM_AL + o00);
                Al[ks][1] = *(const uint32_t*)(smem + SM_AL + o10);
                Al[ks][2] = *(const uint32_t*)(smem + SM_AL + o00 + 16);
                Al[ks][3] = *(const uint32_t*)(smem + SM_AL + o10 + 16);
            }
        }

        float m1a = 3.402823466e38f, m2a = 3.402823466e38f;
        float m1b = 3.402823466e38f, m2b = 3.402823466e38f;
        int   i1a = 0, i1b = 0;

        for (int c0 = 0; c0 < KCB; c0 += CHUNK) {
            __syncthreads();   // protect previous chunk readers
            {
                const float4* srh = (const float4*)(g_cbh + ((size_t)l * KCB + c0) * DIM);
                const float4* srl = (const float4*)(g_cbl + ((size_t)l * KCB + c0) * DIM);
                #pragma unroll
                for (int g = tid; g < CHUNK * 8; g += NTHR) {
                    int row = g >> 3, col = g & 7;
                    *(float4*)(smem + SM_BH + row * STRB + col * 16) = srh[g];
                    *(float4*)(smem + SM_BL + row * STRB + col * 16) = srl[g];
                }
                if (tid < CHUNK) sc2[tid] = g_c2[l * KCB + c0 + tid];
            }
            __syncthreads();

            #pragma unroll 1
            for (int gp = 0; gp < CHUNK / 16; ++gp) {
                float D0[4] = {0.f, 0.f, 0.f, 0.f};
                float D1[4] = {0.f, 0.f, 0.f, 0.f};
                #pragma unroll
                for (int p = 0; p < 2; ++p) {
                    uint32_t bh0[4], bl0[4], bh1[4], bl1[4];
                    uint32_t roff = (uint32_t)((gp * 16 + (lane & 7)) * STRB
                                   + (p * 32 + 8 * (lane >> 3)) * 2);
                    ldsm4(bh0, sb + SM_BH + roff);
                    ldsm4(bl0, sb + SM_BL + roff);
                    ldsm4(bh1, sb + SM_BH + roff + 8 * STRB);
                    ldsm4(bl1, sb + SM_BL + roff + 8 * STRB);
                    #pragma unroll
                    for (int j = 0; j < 2; ++j) {
                        int ks = 2 * p + j;
                        mma16816(D0, Ah[ks], bh0[2*j], bh0[2*j+1]);
                        mma16816(D1, Ah[ks], bh1[2*j], bh1[2*j+1]);
                        mma16816(D0, Ah[ks], bl0[2*j], bl0[2*j+1]);
                        mma16816(D1, Ah[ks], bl1[2*j], bl1[2*j+1]);
                        mma16816(D0, Al[ks], bh0[2*j], bh0[2*j+1]);
                        mma16816(D1, Al[ks], bh1[2*j], bh1[2*j+1]);
                    }
                }
                // epilogue: D holds dot(r, c); dist = c2 - 2*dot
                int cc = (lane & 3) * 2;
                int nb = gp * 16 + cc;
                float2 c2v = *(const float2*)(smem + SM_C2 + nb * 4);
                int gi = c0 + nb;
                track(fmaf(-2.f, D0[0], c2v.x), gi,     m1a, i1a, m2a);
                track(fmaf(-2.f, D0[1], c2v.y), gi + 1, m1a, i1a, m2a);
                track(fmaf(-2.f, D0[2], c2v.x), gi,     m1b, i1b, m2b);
                track(fmaf(-2.f, D0[3], c2v.y), gi + 1, m1b, i1b, m2b);
                float2 c2w = *(const float2*)(smem + SM_C2 + (nb + 8) * 4);
                gi += 8;
                track(fmaf(-2.f, D1[0], c2w.x), gi,     m1a, i1a, m2a);
                track(fmaf(-2.f, D1[1], c2w.y), gi + 1, m1a, i1a, m2a);
                track(fmaf(-2.f, D1[2], c2w.x), gi,     m1b, i1b, m2b);
                track(fmaf(-2.f, D1[3], c2w.y), gi + 1, m1b, i1b, m2b);
            }
        }

        // ---- merge across the 4 lanes of each row quad ----
        #pragma unroll
        for (int mx = 1; mx <= 2; mx <<= 1) {
            float om1 = __shfl_xor_sync(0xffffffffu, m1a, mx);
            float om2 = __shfl_xor_sync(0xffffffffu, m2a, mx);
            int   oi  = __shfl_xor_sync(0xffffffffu, i1a, mx);
            merge3(m1a, i1a, m2a, om1, oi, om2);
            om1 = __shfl_xor_sync(0xffffffffu, m1b, mx);
            om2 = __shfl_xor_sync(0xffffffffu, m2b, mx);
            oi  = __shfl_xor_sync(0xffffffffu, i1b, mx);
            merge3(m1b, i1b, m2b, om1, oi, om2);
        }
        if ((lane & 3) == 0) {
            int vA = warp * 16 + (lane >> 2), vB = vA + 8;
            sidx[vA] = i1a;
            sidx[vB] = i1b;
            if (m2a - m1a < MARGIN) { int p = atomicAdd(nlist, 1); list[p] = vA; }
            if (m2b - m1b < MARGIN) { int p = atomicAdd(nlist, 1); list[p] = vB; }
        }
        __syncthreads();

        // ---- exact fp32 rescue for ambiguous vectors (rare) ----
        int nf = *nlist;
        for (int f = 0; f < nf; ++f) {
            int vr = list[f];
            if (tid == 0) *redk = ~0ull;
            if (v == vr) {
                #pragma unroll
                for (int i = 0; i < 8; ++i)
                    *(float4*)(rstage + h * 32 + 4*i) =
                        make_float4(r[4*i], r[4*i+1], r[4*i+2], r[4*i+3]);
            }
            __syncthreads();
            unsigned long long bk = ~0ull;
            #pragma unroll 1
            for (int c = tid; c < KCB; c += NTHR) {
                const float4* cw = (const float4*)(cb + ((size_t)l * KCB + c) * DIM);
                const float4* rp = (const float4*)rstage;
                float s = 0.f;
                #pragma unroll
                for (int i = 0; i < 16; ++i) {
                    float4 a = rp[i], bq = cw[i];
                    s += a.x*bq.x + a.y*bq.y + a.z*bq.z + a.w*bq.w;
                }
                float dist = fmaf(-2.f, s, g_c2[l * KCB + c]);
                uint32_t fb = __float_as_uint(dist);
                fb ^= (fb & 0x80000000u) ? 0xFFFFFFFFu : 0x80000000u;
                unsigned long long key = ((unsigned long long)fb << 32) | (unsigned)c;
                if (key < bk) bk = key;
            }
            atomicMin(redk, bk);
            __syncthreads();
            if (tid == 0) sidx[vr] = (int)(*redk & 0xffffffffu);
            __syncthreads();
        }

        // ---- commit: residual update, sse, counts, codes ----
        int idx = sidx[v];
        {
            const float4* q = (const float4*)(cb + ((size_t)l * KCB + idx) * DIM + h * 32);
            float sse = 0.f;
            #pragma unroll
            for (int i = 0; i < 8; ++i) {
                float4 qv = q[i];
                r[4*i]   -= qv.x; r[4*i+1] -= qv.y;
                r[4*i+2] -= qv.z; r[4*i+3] -= qv.w;
                sse += r[4*i]*r[4*i] + r[4*i+1]*r[4*i+1]
                     + r[4*i+2]*r[4*i+2] + r[4*i+3]*r[4*i+3];
            }
            double ds = (double)sse;
            #pragma unroll
            for (int o = 16; o; o >>= 1) ds += __shfl_down_sync(0xffffffffu, ds, o);
            if (lane == 0) atomicAdd(&g_mse[l], ds);
        }
        if (h == 0) {
            atomicAdd(&g_counts[l * KCB + idx], 1);
            out[QELEMS + (size_t)l * NVEC + n0 + v] = (float)idx;
        }
        __syncthreads();   // protect staging rewrite next level / rs below
    }

    // ---- quantized = x - final residual (coalesced via shared staging) ----
    float* rs = (float*)(smem + SM_BH);    // 32KB, overlays BH+BL (done with them)
    #pragma unroll
    for (int i = 0; i < 8; ++i)
        *(float4*)(rs + v * 64 + h * 32 + 4*i) =
            make_float4(r[4*i], r[4*i+1], r[4*i+2], r[4*i+3]);
    __syncthreads();
    {
        const float4* xp4 = (const float4*)(x + n0 * DIM);
        const float4* rs4 = (const float4*)rs;
        float4*       op4 = (float4*)(out + n0 * DIM);
        #pragma unroll
        for (int g = tid; g < CTAV * 16; g += NTHR) {
            float4 xv = xp4[g], rv = rs4[g];
            op4[g] = make_float4(xv.x - rv.x, xv.y - rv.y,
                                 xv.z - rv.z, xv.w - rv.w);
        }
    }
}

__global__ void finalize_kernel(float* __restrict__ out) {
    __shared__ double warpsum[8];
    const int t = threadIdx.x;
    double total = 0.0;
    for (int l = 0; l < LEVELS; ++l) {
        float esum = 0.f;
        for (int i = t; i < KCB; i += 256) {
            float p = (float)g_counts[l * KCB + i] / (float)NVEC;
            esum += -(p * logf(p + 1e-10f));
        }
        double e = (double)esum;
        #pragma unroll
        for (int o = 16; o; o >>= 1) e += __shfl_down_sync(0xffffffffu, e, o);
        if ((t & 31) == 0) warpsum[t >> 5] = e;
        __syncthreads();
        if (t == 0) {
            double ent = 0.0;
            #pragma unroll
            for (int w = 0; w < 8; ++w) ent += warpsum[w];
            total += 1.25 * (g_mse[l] / ((double)NVEC * DIM)) + 0.1 * ent;
        }
        __syncthreads();
    }
    if (t == 0) out[QELEMS + (size_t)LEVELS * NVEC] = (float)total;
}

extern "C" void kernel_launch(void* const* d_in, const int* in_sizes, int n_in,
                              void* d_out, int out_size) {
    const float* x  = (const float*)d_in[0];   // [16,8192,64] f32
    const float* cb = (const float*)d_in[1];   // [4,1024,64]  f32
    float* out = (float*)d_out;

    cudaFuncSetAttribute(rvq_mma_kernel,
                         cudaFuncAttributeMaxDynamicSharedMemorySize, SMEM_TOTAL);

    zero_kernel<<<16, 256>>>();
    prep_cb_kernel<<<32, 128>>>(cb);
    rvq_mma_kernel<<<NVEC / CTAV, NTHR, SMEM_TOTAL>>>(x, cb, out);
    finalize_kernel<<<1, 256>>>(out);
}